// round 9
// baseline (speedup 1.0000x reference)
#include <cuda_runtime.h>
#include <math.h>

// Shape (2,3,128,128,128) fp32
#define NTOT   12582912
#define NGRP   12288          // 6*128*16 groups of 8 consecutive y-rows
#define ALPHA  0.001
#define WPB    4
#define BLOCK  (WPB * 32)
#define GRID   (NGRP / WPB)   // 3072

__device__ double       g_acc[3];
__device__ unsigned int g_ticket;

__device__ __forceinline__ float4 f4sub(float4 a, float4 b) {
    return make_float4(a.x - b.x, a.y - b.y, a.z - b.z, a.w - b.w);
}
__device__ __forceinline__ float4 f4add(float4 a, float4 b) {
    return make_float4(a.x + b.x, a.y + b.y, a.z + b.z, a.w + b.w);
}

// One warp per group of 8 consecutive y-rows (fixed vol,z); lane = float4 of x.
// Deep software pipeline: 5 y-levels preloaded; iteration j consumes levels
// j..j+2 and prefetches level j+5 (distance 2+ iterations ahead).
__global__ __launch_bounds__(BLOCK) void ace_main(
    const float* __restrict__ yp, const float* __restrict__ yt,
    float* __restrict__ out)
{
    const unsigned FULL = 0xFFFFFFFFu;
    const int wid  = threadIdx.x >> 5;
    const int lane = threadIdx.x & 31;
    const int g    = blockIdx.x * WPB + wid;

    const int y0  = (g & 15) << 3;          // first of 8 output rows
    const int z   = (g >> 4) & 127;
    const int vol = g >> 11;
    const int zm_ = z > 0   ? z - 1 : 0;
    const int zq  = z < 127 ? z + 1 : 127;

    const float* U = yp + ((size_t)vol << 21);
    const float* T = yt + ((size_t)vol << 21);

    // level l corresponds to y = clamp(y0-1+l), l = 0..9
    float4 cz[10], ez[10], sz[10];
    float4 tv[8];

    #define LOADLVL(l)                                                          \
    {   int yy = y0 - 1 + (l);                                                  \
        yy = yy < 0 ? 0 : (yy > 127 ? 127 : yy);                                \
        const float4 a_ = __ldg(((const float4*)(U + ((zm_ << 14) + (yy << 7)))) + lane); \
        const float4 b_ = __ldg(((const float4*)(U + ((zq  << 14) + (yy << 7)))) + lane); \
        const float4 c_ = __ldg(((const float4*)(U + ((z   << 14) + (yy << 7)))) + lane); \
        cz[l] = c_; ez[l] = f4sub(b_, a_); sz[l] = f4add(b_, a_);               \
    }
    #define LOADT(j)                                                            \
        tv[j] = __ldg(((const float4*)(T + ((z << 14) + ((y0 + (j)) << 7)))) + lane);

    // prologue: 5 levels + 2 t-rows in flight
    LOADLVL(0) LOADLVL(1) LOADLVL(2) LOADLVL(3) LOADLVL(4)
    LOADT(0)   LOADT(1)

    // 6-wide clamped x-window from a float4
    #define MK6(A, V)                                                  \
        float A[6];                                                    \
        A[1] = V.x; A[2] = V.y; A[3] = V.z; A[4] = V.w;                \
        {   float L_ = __shfl_up_sync(FULL, A[4], 1);                  \
            float R_ = __shfl_down_sync(FULL, A[1], 1);                \
            A[0] = (lane == 0)  ? A[1] : L_;                           \
            A[5] = (lane == 31) ? A[4] : R_; }

    float ain = 0.f, aout = 0.f, ael = 0.f;

    #pragma unroll
    for (int j = 0; j < 8; j++) {
        if (j < 5) LOADLVL(j + 5)                  // prefetch, distance >= 2
        if (j < 6) LOADT(j + 2)

        const int l = j + 1;
        const float4 eyv  = f4sub(cz[l + 1], cz[l - 1]);   // u(y+1)-u(y-1)
        const float4 syv  = f4add(cz[l + 1], cz[l - 1]);
        const float4 gxyv = f4sub(ez[l + 1], ez[l - 1]);   // mixed z,y
        const float4 szl  = sz[l];

        MK6(cc,  cz[l])
        MK6(ezw, ez[l])
        MK6(eyw, eyv)

        const float syA [4] = { syv.x,  syv.y,  syv.z,  syv.w  };
        const float szA [4] = { szl.x,  szl.y,  szl.z,  szl.w  };
        const float gxyA[4] = { gxyv.x, gxyv.y, gxyv.z, gxyv.w };
        const float ttA [4] = { tv[j].x, tv[j].y, tv[j].z, tv[j].w };

        #pragma unroll
        for (int k = 0; k < 4; k++) {
            const float uc = cc[k + 1];
            const float di = ezw[k + 1];
            const float dj = eyw[k + 1];
            const float dk = cc[k + 2] - cc[k];

            const float cii = fmaf(uc, -2.f, szA[k]);
            const float cjj = fmaf(uc, -2.f, syA[k]);
            const float ckk = fmaf(uc, -2.f, cc[k] + cc[k + 2]);
            const float lap = cii + cjj + ckk;

            const float Dik = ezw[k + 2] - ezw[k];
            const float Djk = eyw[k + 2] - eyw[k];
            const float Dij = gxyA[k];

            const float di2 = di * di, dj2 = dj * dj, dk2 = dk * dk;
            const float S = di2 + dj2 + dk2;             // = 4*(ci2+cj2+ck2)

            float acc = di2 * cii;
            acc = fmaf(dj2, cjj, acc);
            acc = fmaf(dk2, ckk, acc);
            acc = fmaf(Dik * Djk, Dij, acc);
            const float curv = fmaf(0.25f, fmaf(S, lap, -acc), lap);

            const float ee = fmaf(0.25f, S, 1e-8f);      // eps + s
            const float oo = fmaf(0.25f, S, 1.f);        // (sqrt(1+s)+eps)^2 ~ 1+s
            ael += __fdividef(curv * curv * sqrtf(ee), oo);

            const float t = ttA[k];
            const float tm1 = t - 1.f;
            ain  = fmaf(uc, tm1 * tm1, ain);
            aout = fmaf(1.f - uc, t * t, aout);
        }
    }
    #undef MK6
    #undef LOADLVL
    #undef LOADT

    // ---- block reduction ----
    #pragma unroll
    for (int o = 16; o > 0; o >>= 1) {
        ain  += __shfl_down_sync(FULL, ain,  o);
        aout += __shfl_down_sync(FULL, aout, o);
        ael  += __shfl_down_sync(FULL, ael,  o);
    }
    __shared__ float si[WPB], so[WPB], se[WPB];
    if (lane == 0) { si[wid] = ain; so[wid] = aout; se[wid] = ael; }
    __syncthreads();

    if (threadIdx.x == 0) {
        float A = si[0] + si[1] + si[2] + si[3];
        float B = so[0] + so[1] + so[2] + so[3];
        float E = se[0] + se[1] + se[2] + se[3];
        atomicAdd(&g_acc[0], (double)A);
        atomicAdd(&g_acc[1], (double)B);
        atomicAdd(&g_acc[2], (double)E);
        __threadfence();
        unsigned t = atomicAdd(&g_ticket, 1u);
        if (t == (unsigned)(GRID - 1)) {          // last block finalizes + resets
            __threadfence();
            double s0 = atomicAdd(&g_acc[0], 0.0);
            double s1 = atomicAdd(&g_acc[1], 0.0);
            double s2 = atomicAdd(&g_acc[2], 0.0);
            double res = fabs(s0) + fabs(s1) + s2 + ALPHA * (double)NTOT;
            out[0] = (float)res;
            g_acc[0] = 0.0; g_acc[1] = 0.0; g_acc[2] = 0.0;
            g_ticket = 0u;
        }
    }
}

extern "C" void kernel_launch(void* const* d_in, const int* in_sizes, int n_in,
                              void* d_out, int out_size) {
    const float* y_pred = (const float*)d_in[0];
    const float* y_true = (const float*)d_in[1];
    ace_main<<<GRID, BLOCK>>>(y_pred, y_true, (float*)d_out);
}

// round 10
// speedup vs baseline: 1.2323x; 1.2323x over previous
#include <cuda_runtime.h>
#include <math.h>

// Shape (2,3,128,128,128) fp32
#define NTOT   12582912
#define NGRP   24576          // 6*128*32 groups of 4 consecutive y-rows
#define ALPHA  0.001
#define WPB    4
#define BLOCK  (WPB * 32)
#define GRID   (NGRP / WPB)   // 6144

__device__ double       g_acc[3];
__device__ unsigned int g_ticket;

__device__ __forceinline__ float4 f4sub(float4 a, float4 b) {
    return make_float4(a.x - b.x, a.y - b.y, a.z - b.z, a.w - b.w);
}
__device__ __forceinline__ float4 f4add(float4 a, float4 b) {
    return make_float4(a.x + b.x, a.y + b.y, a.z + b.z, a.w + b.w);
}

// One warp per group of 4 consecutive y-rows (fixed vol,z); lane = float4 of x.
// 4 levels preloaded, 2 prefetched in-loop; t-rows prefetched distance 1.
__global__ __launch_bounds__(BLOCK, 6) void ace_main(
    const float* __restrict__ yp, const float* __restrict__ yt,
    float* __restrict__ out)
{
    const unsigned FULL = 0xFFFFFFFFu;
    const int wid  = threadIdx.x >> 5;
    const int lane = threadIdx.x & 31;
    const int g    = blockIdx.x * WPB + wid;

    const int y0  = (g & 31) << 2;          // first of 4 output rows
    const int z   = (g >> 5) & 127;
    const int vol = g >> 12;
    const int zm_ = z > 0   ? z - 1 : 0;
    const int zq  = z < 127 ? z + 1 : 127;

    const float* U = yp + ((size_t)vol << 21);
    const float* T = yt + ((size_t)vol << 21);

    // level l corresponds to y = clamp(y0-1+l), l = 0..5
    float4 cz[6], ez[6], sz[6];
    float4 tv[4];

    #define LOADLVL(l)                                                          \
    {   int yy = y0 - 1 + (l);                                                  \
        yy = yy < 0 ? 0 : (yy > 127 ? 127 : yy);                                \
        const float4 a_ = __ldg(((const float4*)(U + ((zm_ << 14) + (yy << 7)))) + lane); \
        const float4 b_ = __ldg(((const float4*)(U + ((zq  << 14) + (yy << 7)))) + lane); \
        const float4 c_ = __ldg(((const float4*)(U + ((z   << 14) + (yy << 7)))) + lane); \
        cz[l] = c_; ez[l] = f4sub(b_, a_); sz[l] = f4add(b_, a_);               \
    }
    #define LOADT(j)                                                            \
        tv[j] = __ldg(((const float4*)(T + ((z << 14) + ((y0 + (j)) << 7)))) + lane);

    LOADLVL(0) LOADLVL(1) LOADLVL(2) LOADLVL(3)
    LOADT(0)

    // 6-wide clamped x-window from a float4
    #define MK6(A, V)                                                  \
        float A[6];                                                    \
        A[1] = V.x; A[2] = V.y; A[3] = V.z; A[4] = V.w;                \
        {   float L_ = __shfl_up_sync(FULL, A[4], 1);                  \
            float R_ = __shfl_down_sync(FULL, A[1], 1);                \
            A[0] = (lane == 0)  ? A[1] : L_;                           \
            A[5] = (lane == 31) ? A[4] : R_; }

    float ain = 0.f, aout = 0.f, ael = 0.f;

    #pragma unroll
    for (int j = 0; j < 4; j++) {
        if (j < 2) LOADLVL(j + 4)                  // prefetch remaining levels
        if (j < 3) LOADT(j + 1)                    // t prefetch, distance 1

        const int l = j + 1;
        const float4 eyv  = f4sub(cz[l + 1], cz[l - 1]);   // u(y+1)-u(y-1)
        const float4 syv  = f4add(cz[l + 1], cz[l - 1]);
        const float4 gxyv = f4sub(ez[l + 1], ez[l - 1]);   // mixed z,y
        const float4 szl  = sz[l];

        MK6(cc,  cz[l])
        MK6(ezw, ez[l])
        MK6(eyw, eyv)

        const float syA [4] = { syv.x,  syv.y,  syv.z,  syv.w  };
        const float szA [4] = { szl.x,  szl.y,  szl.z,  szl.w  };
        const float gxyA[4] = { gxyv.x, gxyv.y, gxyv.z, gxyv.w };
        const float ttA [4] = { tv[j].x, tv[j].y, tv[j].z, tv[j].w };

        #pragma unroll
        for (int k = 0; k < 4; k++) {
            const float uc = cc[k + 1];
            const float di = ezw[k + 1];
            const float dj = eyw[k + 1];
            const float dk = cc[k + 2] - cc[k];

            const float cii = fmaf(uc, -2.f, szA[k]);
            const float cjj = fmaf(uc, -2.f, syA[k]);
            const float ckk = fmaf(uc, -2.f, cc[k] + cc[k + 2]);
            const float lap = cii + cjj + ckk;

            const float Dik = ezw[k + 2] - ezw[k];
            const float Djk = eyw[k + 2] - eyw[k];
            const float Dij = gxyA[k];

            const float di2 = di * di, dj2 = dj * dj, dk2 = dk * dk;
            const float S = di2 + dj2 + dk2;             // = 4*(ci2+cj2+ck2)

            float acc = di2 * cii;
            acc = fmaf(dj2, cjj, acc);
            acc = fmaf(dk2, ckk, acc);
            acc = fmaf(Dik * Djk, Dij, acc);
            const float curv = fmaf(0.25f, fmaf(S, lap, -acc), lap);

            const float ee = fmaf(0.25f, S, 1e-8f);      // eps + s
            const float oo = fmaf(0.25f, S, 1.f);        // (sqrt(1+s)+eps)^2 ~ 1+s
            // sqrt(ee)/oo == ee * rsqrt(ee*oo^2)  (one MUFU.RSQ, no div/sqrt)
            const float r_ = rsqrtf(ee * oo * oo);
            ael = fmaf(curv * curv * ee, r_, ael);

            const float t = ttA[k];
            const float tm1 = t - 1.f;
            ain  = fmaf(uc, tm1 * tm1, ain);
            aout = fmaf(1.f - uc, t * t, aout);
        }
    }
    #undef MK6
    #undef LOADLVL
    #undef LOADT

    // ---- block reduction ----
    #pragma unroll
    for (int o = 16; o > 0; o >>= 1) {
        ain  += __shfl_down_sync(FULL, ain,  o);
        aout += __shfl_down_sync(FULL, aout, o);
        ael  += __shfl_down_sync(FULL, ael,  o);
    }
    __shared__ float si[WPB], so[WPB], se[WPB];
    if (lane == 0) { si[wid] = ain; so[wid] = aout; se[wid] = ael; }
    __syncthreads();

    if (threadIdx.x == 0) {
        float A = si[0] + si[1] + si[2] + si[3];
        float B = so[0] + so[1] + so[2] + so[3];
        float E = se[0] + se[1] + se[2] + se[3];
        atomicAdd(&g_acc[0], (double)A);
        atomicAdd(&g_acc[1], (double)B);
        atomicAdd(&g_acc[2], (double)E);
        __threadfence();
        unsigned t = atomicAdd(&g_ticket, 1u);
        if (t == (unsigned)(GRID - 1)) {          // last block finalizes + resets
            __threadfence();
            double s0 = atomicAdd(&g_acc[0], 0.0);
            double s1 = atomicAdd(&g_acc[1], 0.0);
            double s2 = atomicAdd(&g_acc[2], 0.0);
            double res = fabs(s0) + fabs(s1) + s2 + ALPHA * (double)NTOT;
            out[0] = (float)res;
            g_acc[0] = 0.0; g_acc[1] = 0.0; g_acc[2] = 0.0;
            g_ticket = 0u;
        }
    }
}

extern "C" void kernel_launch(void* const* d_in, const int* in_sizes, int n_in,
                              void* d_out, int out_size) {
    const float* y_pred = (const float*)d_in[0];
    const float* y_true = (const float*)d_in[1];
    ace_main<<<GRID, BLOCK>>>(y_pred, y_true, (float*)d_out);
}